// round 1
// baseline (speedup 1.0000x reference)
#include <cuda_runtime.h>

#define BB 8
#define CC 64
#define HH 128
#define WW 128
#define OCC 64
#define KK 9
#define HOO 128
#define WOO 128
#define CKD 576   // C*K
#define TP 32     // pixels per block

struct Meta { int4 off; float4 w; };

__global__ __launch_bounds__(256, 2)
void dcn_fused_kernel(const float* __restrict__ input,
                      const float* __restrict__ offset,
                      const float* __restrict__ mask,
                      const float* __restrict__ weight,
                      const float* __restrict__ bias,
                      float* __restrict__ out)
{
    extern __shared__ float smem[];
    float* cols = smem;                          // [CKD][TP] = 18432 floats
    Meta*  meta = (Meta*)(smem + CKD * TP);      // [K*TP] = 288 * 32B (phase A only)
    float* w_s  = smem + CKD * TP;               // [64][64] = 4096 floats (phase B)

    const int tid = threadIdx.x;
    const int x0  = blockIdx.x * TP;
    const int y   = blockIdx.y;
    const int b   = blockIdx.z;

    // ---------------- Phase A1: per-(tap,pixel) bilinear meta ----------------
    for (int idx = tid; idx < KK * TP; idx += 256) {
        int k = idx >> 5;
        int p = idx & 31;
        int x = x0 + p;
        int obase = ((b * 18 + 2 * k) * HOO + y) * WOO + x;
        float dy = offset[obase];
        float dx = offset[obase + HOO * WOO];
        float m  = mask[((b * KK + k) * HOO + y) * WOO + x];
        int ky = k / 3, kx = k - 3 * (k / 3);
        float py = (float)(y - 1 + ky) + dy;
        float px = (float)(x - 1 + kx) + dx;
        float fy = floorf(py), fx = floorf(px);
        int iy0 = (int)fy, ix0 = (int)fx;
        float wy1 = py - fy, wx1 = px - fx;
        float wy0 = 1.0f - wy1, wx0 = 1.0f - wx1;
        int iy1 = iy0 + 1, ix1 = ix0 + 1;
        bool vy0 = (iy0 >= 0) && (iy0 < HH);
        bool vy1 = (iy1 >= 0) && (iy1 < HH);
        bool vx0 = (ix0 >= 0) && (ix0 < WW);
        bool vx1 = (ix1 >= 0) && (ix1 < WW);
        int cy0 = min(max(iy0, 0), HH - 1), cy1 = min(max(iy1, 0), HH - 1);
        int cx0 = min(max(ix0, 0), WW - 1), cx1 = min(max(ix1, 0), WW - 1);
        Meta mt;
        mt.off = make_int4(cy0 * WW + cx0, cy0 * WW + cx1,
                           cy1 * WW + cx0, cy1 * WW + cx1);
        mt.w = make_float4((vy0 && vx0) ? m * wy0 * wx0 : 0.0f,
                           (vy0 && vx1) ? m * wy0 * wx1 : 0.0f,
                           (vy1 && vx0) ? m * wy1 * wx0 : 0.0f,
                           (vy1 && vx1) ? m * wy1 * wx1 : 0.0f);
        meta[idx] = mt;
    }
    __syncthreads();

    // ---------------- Phase A2: channel sweep -> cols in smem ----------------
    const float* inB = input + (size_t)b * CC * HH * WW;
    for (int i = tid; i < CC * KK * TP; i += 256) {
        int c  = i / (KK * TP);
        int kp = i - c * (KK * TP);
        Meta mt = meta[kp];
        const float* pl = inB + c * HH * WW;
        float v = mt.w.x * __ldg(pl + mt.off.x)
                + mt.w.y * __ldg(pl + mt.off.y)
                + mt.w.z * __ldg(pl + mt.off.z)
                + mt.w.w * __ldg(pl + mt.off.w);
        int k = kp >> 5, p = kp & 31;
        cols[(c * KK + k) * TP + p] = v;
    }
    __syncthreads();

    // ---------------- Phase B: 64x32 GEMM over CK=576 ----------------
    const int p   = tid & 31;     // pixel lane
    const int wg  = tid >> 5;     // oc group 0..7
    const int ocb = wg * 8;
    float acc[8];
    #pragma unroll
    for (int i = 0; i < 8; i++) acc[i] = bias[ocb + i];

    for (int cc = 0; cc < 9; cc++) {
        // stage 64x64 weight chunk (row-contiguous loads, broadcast reads later)
        for (int idx = tid; idx < 64 * 64; idx += 256) {
            int oc = idx >> 6, ckl = idx & 63;
            w_s[idx] = weight[oc * CKD + cc * 64 + ckl];
        }
        __syncthreads();
        #pragma unroll
        for (int q = 0; q < 16; q++) {
            int ck = cc * 64 + q * 4;
            float4 cv;
            cv.x = cols[(ck + 0) * TP + p];
            cv.y = cols[(ck + 1) * TP + p];
            cv.z = cols[(ck + 2) * TP + p];
            cv.w = cols[(ck + 3) * TP + p];
            #pragma unroll
            for (int i = 0; i < 8; i++) {
                float4 wv = *(const float4*)&w_s[(ocb + i) * 64 + q * 4];
                acc[i] = fmaf(wv.x, cv.x,
                         fmaf(wv.y, cv.y,
                         fmaf(wv.z, cv.z,
                         fmaf(wv.w, cv.w, acc[i]))));
            }
        }
        __syncthreads();
    }

    #pragma unroll
    for (int i = 0; i < 8; i++) {
        out[((size_t)(b * OCC + ocb + i) * HOO + y) * WOO + x0 + p] = acc[i];
    }
}

extern "C" void kernel_launch(void* const* d_in, const int* in_sizes, int n_in,
                              void* d_out, int out_size) {
    const float* input  = (const float*)d_in[0];
    const float* offset = (const float*)d_in[1];
    const float* mask   = (const float*)d_in[2];
    const float* weight = (const float*)d_in[3];
    const float* bias   = (const float*)d_in[4];
    float* out = (float*)d_out;

    const int smem_bytes = (CKD * TP + 64 * 64) * (int)sizeof(float); // 90112
    cudaFuncSetAttribute(dcn_fused_kernel,
                         cudaFuncAttributeMaxDynamicSharedMemorySize, smem_bytes);

    dim3 grid(WOO / TP, HOO, BB);
    dcn_fused_kernel<<<grid, 256, smem_bytes>>>(input, offset, mask, weight, bias, out);
}

// round 2
// speedup vs baseline: 1.6436x; 1.6436x over previous
#include <cuda_runtime.h>

#define BB 8
#define CC 64
#define HH 128
#define WW 128
#define OCC 64
#define KK 9
#define HOO 128
#define WOO 128
#define CKD 576        // C*K
#define TPX 128        // pixels per block (one full output row)
#define CHK 72         // ck per chunk = 8 channels * 9 taps
#define NCHK 8         // 576 / 72

__global__ __launch_bounds__(256, 2)
void dcn_fused_kernel(const float* __restrict__ input,
                      const float* __restrict__ offset,
                      const float* __restrict__ mask,
                      const float* __restrict__ weight,
                      const float* __restrict__ bias,
                      float* __restrict__ out)
{
    extern __shared__ float smem[];
    float* cols = smem;                                   // [CHK][TPX]   36864 B
    float* w_s  = smem + CHK * TPX;                       // [64][CHK]    18432 B
    int4*  offs = (int4*)(smem + CHK * TPX + 64 * CHK);   // [KK*TPX]     18432 B
    float4* wts = (float4*)((char*)offs + KK * TPX * 16); // [KK*TPX]     18432 B

    const int tid = threadIdx.x;
    const int y   = blockIdx.y;
    const int b   = blockIdx.z;

    // ---------------- Phase A1: bilinear meta for all 9 taps x 128 px ----------------
    for (int idx = tid; idx < KK * TPX; idx += 256) {
        int k = idx >> 7;          // tap
        int x = idx & 127;         // pixel
        int obase = ((b * 18 + 2 * k) * HOO + y) * WOO + x;
        float dy = offset[obase];
        float dx = offset[obase + HOO * WOO];
        float m  = mask[((b * KK + k) * HOO + y) * WOO + x];
        int ky = k / 3, kx = k - 3 * (k / 3);
        float py = (float)(y - 1 + ky) + dy;
        float px = (float)(x - 1 + kx) + dx;
        float fy = floorf(py), fx = floorf(px);
        int iy0 = (int)fy, ix0 = (int)fx;
        float wy1 = py - fy, wx1 = px - fx;
        float wy0 = 1.0f - wy1, wx0 = 1.0f - wx1;
        int iy1 = iy0 + 1, ix1 = ix0 + 1;
        bool vy0 = (iy0 >= 0) && (iy0 < HH);
        bool vy1 = (iy1 >= 0) && (iy1 < HH);
        bool vx0 = (ix0 >= 0) && (ix0 < WW);
        bool vx1 = (ix1 >= 0) && (ix1 < WW);
        int cy0 = min(max(iy0, 0), HH - 1), cy1 = min(max(iy1, 0), HH - 1);
        int cx0 = min(max(ix0, 0), WW - 1), cx1 = min(max(ix1, 0), WW - 1);
        offs[idx] = make_int4(cy0 * WW + cx0, cy0 * WW + cx1,
                              cy1 * WW + cx0, cy1 * WW + cx1);
        wts[idx] = make_float4((vy0 && vx0) ? m * wy0 * wx0 : 0.0f,
                               (vy0 && vx1) ? m * wy0 * wx1 : 0.0f,
                               (vy1 && vx0) ? m * wy1 * wx0 : 0.0f,
                               (vy1 && vx1) ? m * wy1 * wx1 : 0.0f);
    }
    __syncthreads();

    // ---------------- register tile: 8 oc x 4 px per thread ----------------
    const int lane = tid & 31;         // pixel lane (pixels lane, lane+32, lane+64, lane+96)
    const int wg   = tid >> 5;         // oc group
    const int ocb  = wg * 8;

    float acc[8][4];
    #pragma unroll
    for (int i = 0; i < 8; i++) {
        float bv = bias[ocb + i];
        #pragma unroll
        for (int j = 0; j < 4; j++) acc[i][j] = bv;
    }

    const float* inB = input + (size_t)b * CC * HH * WW;

    for (int cc = 0; cc < NCHK; cc++) {
        const int ckbase = cc * CHK;
        const int cbase  = cc * 8;

        // stage weight chunk [64 oc][72 ck]
        #pragma unroll
        for (int t = 0; t < 18; t++) {
            int idx = t * 256 + tid;            // 0..4607
            int oc = idx / CHK;
            int j  = idx - oc * CHK;
            w_s[idx] = weight[oc * CKD + ckbase + j];
        }

        // build cols chunk [72 ck][128 px]
        #pragma unroll 4
        for (int it = 0; it < 36; it++) {
            int ckl = 2 * it + (tid >> 7);       // 0..71
            int p   = tid & 127;
            int c   = cbase + ckl / KK;
            int k   = ckl - KK * (ckl / KK);
            int mi  = (k << 7) + p;
            int4   o = offs[mi];
            float4 w = wts[mi];
            const float* pl = inB + c * HH * WW;
            cols[(ckl << 7) + p] =
                  w.x * __ldg(pl + o.x)
                + w.y * __ldg(pl + o.y)
                + w.z * __ldg(pl + o.z)
                + w.w * __ldg(pl + o.w);
        }
        __syncthreads();

        // GEMM over this chunk: 18 steps of 4 k
        #pragma unroll
        for (int q = 0; q < 18; q++) {
            float cv[4][4];
            #pragma unroll
            for (int kk = 0; kk < 4; kk++) {
                #pragma unroll
                for (int j = 0; j < 4; j++)
                    cv[kk][j] = cols[((q * 4 + kk) << 7) + lane + 32 * j];
            }
            #pragma unroll
            for (int i = 0; i < 8; i++) {
                float4 wv = *(const float4*)&w_s[(ocb + i) * CHK + q * 4];
                #pragma unroll
                for (int j = 0; j < 4; j++) {
                    acc[i][j] = fmaf(wv.x, cv[0][j],
                                fmaf(wv.y, cv[1][j],
                                fmaf(wv.z, cv[2][j],
                                fmaf(wv.w, cv[3][j], acc[i][j]))));
                }
            }
        }
        __syncthreads();
    }

    // ---------------- store 8 oc x 4 px ----------------
    #pragma unroll
    for (int i = 0; i < 8; i++) {
        #pragma unroll
        for (int j = 0; j < 4; j++) {
            out[((size_t)(b * OCC + ocb + i) * HOO + y) * WOO + lane + 32 * j] = acc[i][j];
        }
    }
}

extern "C" void kernel_launch(void* const* d_in, const int* in_sizes, int n_in,
                              void* d_out, int out_size) {
    const float* input  = (const float*)d_in[0];
    const float* offset = (const float*)d_in[1];
    const float* mask   = (const float*)d_in[2];
    const float* weight = (const float*)d_in[3];
    const float* bias   = (const float*)d_in[4];
    float* out = (float*)d_out;

    const int smem_bytes = (CHK * TPX + 64 * CHK) * 4 + KK * TPX * 32; // 92160
    cudaFuncSetAttribute(dcn_fused_kernel,
                         cudaFuncAttributeMaxDynamicSharedMemorySize, smem_bytes);

    dim3 grid(1, HOO, BB);
    dcn_fused_kernel<<<grid, 256, smem_bytes>>>(input, offset, mask, weight, bias, out);
}

// round 4
// speedup vs baseline: 2.8730x; 1.7480x over previous
#include <cuda_runtime.h>
#include <cuda_bf16.h>
#include <cstdint>

#define BB 8
#define CCH 64
#define HH 128
#define WW 128
#define OCC 64
#define KT 9
#define HW (HH * WW)
#define AST 72     // A smem row stride in bf16 (144B: 16B-aligned, conflict-free ldmatrix)
#define BST 72     // B smem row stride in bf16

// ---------------- device scratch (no allocations allowed) ----------------
__device__ __align__(256) float    g_nhwc[BB * HH * WW * CCH];       // 33.5 MB
__device__ __align__(16)  uint32_t g_whi[OCC * KT * CCH / 2];        // bf16 pairs [oc][tap][cpair]
__device__ __align__(16)  uint32_t g_wlo[OCC * KT * CCH / 2];

__device__ __forceinline__ uint32_t smem_u32(const void* p) {
    uint32_t a;
    asm("{ .reg .u64 t; cvta.to.shared.u64 t, %1; cvt.u32.u64 %0, t; }" : "=r"(a) : "l"(p));
    return a;
}

#define LDSM_X4(r0, r1, r2, r3, addr) \
    asm volatile("ldmatrix.sync.aligned.m8n8.x4.shared.b16 {%0,%1,%2,%3}, [%4];" \
                 : "=r"(r0), "=r"(r1), "=r"(r2), "=r"(r3) : "r"(addr))
#define LDSM_X2(r0, r1, addr) \
    asm volatile("ldmatrix.sync.aligned.m8n8.x2.shared.b16 {%0,%1}, [%2];" \
                 : "=r"(r0), "=r"(r1) : "r"(addr))
#define MMA16816(d, a0, a1, a2, a3, b0, b1) \
    asm volatile("mma.sync.aligned.m16n8k16.row.col.f32.bf16.bf16.f32 " \
                 "{%0,%1,%2,%3}, {%4,%5,%6,%7}, {%8,%9}, {%0,%1,%2,%3};" \
                 : "+f"((d)[0]), "+f"((d)[1]), "+f"((d)[2]), "+f"((d)[3]) \
                 : "r"(a0), "r"(a1), "r"(a2), "r"(a3), "r"(b0), "r"(b1))

// ---------------- smem layout (bytes) ----------------
#define SM_AHI  0
#define SM_ALO  (SM_AHI + 128 * AST * 2)      // 18432
#define SM_BHI  (SM_ALO + 128 * AST * 2)      // 36864
#define SM_BLO  (SM_BHI + 64 * BST * 2)       // 46080
#define SM_OFFS (SM_BLO + 64 * BST * 2)       // 55296  int4[KT*128]
#define SM_WTS  (SM_OFFS + KT * 128 * 16)     // 73728  float4[KT*128]
#define SM_TOTAL (SM_WTS + KT * 128 * 16)     // 92160

// ================= prep 1: NCHW -> NHWC =================
__global__ void nhwc_kernel(const float* __restrict__ in) {
    __shared__ float tile[CCH][HH + 1];
    int b = blockIdx.x >> 7, y = blockIdx.x & 127;
    const float* src = in + (size_t)b * CCH * HW + y * WW;
    #pragma unroll
    for (int it = 0; it < 32; it++) {
        int idx = it * 256 + threadIdx.x;
        int c = idx >> 7, x = idx & 127;
        tile[c][x] = src[(size_t)c * HW + x];
    }
    __syncthreads();
    float* dst = g_nhwc + ((size_t)(b * HH + y) * WW) * CCH;
    #pragma unroll
    for (int it = 0; it < 32; it++) {
        int idx = it * 256 + threadIdx.x;
        int x = idx >> 6, c = idx & 63;
        dst[x * CCH + c] = tile[c][x];
    }
}

// ================= prep 2: weight -> [oc][tap][c] bf16 hi/lo pairs =================
__global__ void wprep_kernel(const float* __restrict__ w) {
    int idx = blockIdx.x * 256 + threadIdx.x;     // 0 .. 18431 uint32 slots
    if (idx < OCC * KT * CCH / 2) {
        int oc  = idx / (KT * 32);
        int r   = idx - oc * (KT * 32);
        int tap = r >> 5;
        int j   = r & 31;
        int c0 = 2 * j;
        float v0 = w[(oc * CCH + c0) * KT + tap];
        float v1 = w[(oc * CCH + c0 + 1) * KT + tap];
        __nv_bfloat16 h0 = __float2bfloat16(v0);
        __nv_bfloat16 h1 = __float2bfloat16(v1);
        __nv_bfloat16 l0 = __float2bfloat16(v0 - __bfloat162float(h0));
        __nv_bfloat16 l1 = __float2bfloat16(v1 - __bfloat162float(h1));
        g_whi[idx] = ((uint32_t)__bfloat16_as_ushort(h1) << 16) | __bfloat16_as_ushort(h0);
        g_wlo[idx] = ((uint32_t)__bfloat16_as_ushort(l1) << 16) | __bfloat16_as_ushort(l0);
    }
}

// ================= main fused kernel =================
__global__ __launch_bounds__(256, 2)
void dcn_mma_kernel(const float* __restrict__ offset,
                    const float* __restrict__ mask,
                    const float* __restrict__ bias,
                    float* __restrict__ out)
{
    extern __shared__ char smem[];
    const uint32_t sb = smem_u32(smem);
    const int tid  = threadIdx.x;
    const int wid  = tid >> 5;
    const int lane = tid & 31;
    const int y = blockIdx.y;
    const int b = blockIdx.z;

    // ---- bilinear meta for 9 taps x 128 px (NHWC site offsets) ----
    int4*   offs = (int4*)(smem + SM_OFFS);
    float4* wts  = (float4*)(smem + SM_WTS);
    for (int idx = tid; idx < KT * 128; idx += 256) {
        int k = idx >> 7;
        int x = idx & 127;
        int obase = ((b * 18 + 2 * k) * HH + y) * WW + x;
        float dy = offset[obase];
        float dx = offset[obase + HW];
        float m  = mask[((b * KT + k) * HH + y) * WW + x];
        int ky = k / 3, kx = k - 3 * (k / 3);
        float py = (float)(y - 1 + ky) + dy;
        float px = (float)(x - 1 + kx) + dx;
        float fy = floorf(py), fx = floorf(px);
        int iy0 = (int)fy, ix0 = (int)fx;
        float wy1 = py - fy, wx1 = px - fx;
        float wy0 = 1.0f - wy1, wx0 = 1.0f - wx1;
        int iy1 = iy0 + 1, ix1 = ix0 + 1;
        bool vy0 = (iy0 >= 0) && (iy0 < HH);
        bool vy1 = (iy1 >= 0) && (iy1 < HH);
        bool vx0 = (ix0 >= 0) && (ix0 < WW);
        bool vx1 = (ix1 >= 0) && (ix1 < WW);
        int cy0 = min(max(iy0, 0), HH - 1), cy1 = min(max(iy1, 0), HH - 1);
        int cx0 = min(max(ix0, 0), WW - 1), cx1 = min(max(ix1, 0), WW - 1);
        offs[idx] = make_int4((cy0 * WW + cx0) * CCH, (cy0 * WW + cx1) * CCH,
                              (cy1 * WW + cx0) * CCH, (cy1 * WW + cx1) * CCH);
        wts[idx] = make_float4((vy0 && vx0) ? m * wy0 * wx0 : 0.0f,
                               (vy0 && vx1) ? m * wy0 * wx1 : 0.0f,
                               (vy1 && vx0) ? m * wy1 * wx0 : 0.0f,
                               (vy1 && vx1) ? m * wy1 * wx1 : 0.0f);
    }

    // ---- accumulators: warp tile 16 px x 64 oc ----
    // d frag (m16n8): d0,d1 = row l/4,  cols 2(l%4), 2(l%4)+1 ; d2,d3 = row l/4+8
    float acc[8][4];
    {
        int oc0 = 2 * (lane & 3);
        #pragma unroll
        for (int nb = 0; nb < 8; nb++) {
            float b0 = bias[nb * 8 + oc0];
            float b1 = bias[nb * 8 + oc0 + 1];
            acc[nb][0] = b0; acc[nb][1] = b1;
            acc[nb][2] = b0; acc[nb][3] = b1;
        }
    }

    // per-lane ldmatrix base offsets (bytes)
    const uint32_t a_lane = ((lane & 15) * AST + ((lane >> 1) & 8)) * 2;
    const uint32_t b_lane = ((lane & 7) * BST + (lane & 8)) * 2;
    const uint32_t a_hi_base = sb + SM_AHI + wid * 16 * AST * 2 + a_lane;
    const uint32_t a_lo_base = sb + SM_ALO + wid * 16 * AST * 2 + a_lane;
    const uint32_t b_hi_base = sb + SM_BHI + b_lane;
    const uint32_t b_lo_base = sb + SM_BLO + b_lane;

    const float* nb_ptr = g_nhwc + (size_t)b * HW * CCH;
    __syncthreads();

    for (int tap = 0; tap < KT; tap++) {
        if (tap) __syncthreads();   // previous tap's ldmatrix reads done

        // ---- stage B chunk [64 oc][64 c] hi/lo ----
        #pragma unroll
        for (int it = 0; it < 8; it++) {
            int idx = it * 256 + tid;          // 0..2047 uint32 slots
            int oc = idx >> 5;
            int j  = idx & 31;
            int src = (oc * KT + tap) * 32 + j;
            uint32_t doff = (uint32_t)(oc * BST * 2 + j * 4);
            *(uint32_t*)(smem + SM_BHI + doff) = g_whi[src];
            *(uint32_t*)(smem + SM_BLO + doff) = g_wlo[src];
        }

        // ---- sample A chunk [128 px][64 c] hi/lo: lane = channel pair ----
        #pragma unroll 2
        for (int i = 0; i < 16; i++) {
            int px = wid * 16 + i;
            int mi = (tap << 7) + px;
            int4   o = offs[mi];     // warp-broadcast
            float4 w = wts[mi];
            const float2 c00 = *(const float2*)(nb_ptr + o.x + 2 * lane);
            const float2 c01 = *(const float2*)(nb_ptr + o.y + 2 * lane);
            const float2 c10 = *(const float2*)(nb_ptr + o.z + 2 * lane);
            const float2 c11 = *(const float2*)(nb_ptr + o.w + 2 * lane);
            float vx = w.x * c00.x + w.y * c01.x + w.z * c10.x + w.w * c11.x;
            float vy = w.x * c00.y + w.y * c01.y + w.z * c10.y + w.w * c11.y;
            __nv_bfloat16 hx = __float2bfloat16(vx);
            __nv_bfloat16 hy = __float2bfloat16(vy);
            __nv_bfloat16 lx = __float2bfloat16(vx - __bfloat162float(hx));
            __nv_bfloat16 ly = __float2bfloat16(vy - __bfloat162float(hy));
            uint32_t hp = ((uint32_t)__bfloat16_as_ushort(hy) << 16) | __bfloat16_as_ushort(hx);
            uint32_t lp = ((uint32_t)__bfloat16_as_ushort(ly) << 16) | __bfloat16_as_ushort(lx);
            uint32_t doff = (uint32_t)(px * AST * 2 + lane * 4);
            *(uint32_t*)(smem + SM_AHI + doff) = hp;
            *(uint32_t*)(smem + SM_ALO + doff) = lp;
        }
        __syncthreads();

        // ---- warp GEMM: 4 ksteps of k16 over this tap's 64 channels ----
        #pragma unroll
        for (int ks = 0; ks < 4; ks++) {
            const uint32_t kb = ks * 32;    // 16 bf16 = 32 bytes
            uint32_t ah0, ah1, ah2, ah3, al0, al1, al2, al3;
            LDSM_X4(ah0, ah1, ah2, ah3, a_hi_base + kb);
            LDSM_X4(al0, al1, al2, al3, a_lo_base + kb);
            #pragma unroll
            for (int nb = 0; nb < 8; nb++) {
                const uint32_t boff = (uint32_t)(nb * 8 * BST * 2) + kb;
                uint32_t bh0, bh1, bl0, bl1;
                LDSM_X2(bh0, bh1, b_hi_base + boff);
                LDSM_X2(bl0, bl1, b_lo_base + boff);
                MMA16816(acc[nb], ah0, ah1, ah2, ah3, bh0, bh1);
                MMA16816(acc[nb], ah0, ah1, ah2, ah3, bl0, bl1);
                MMA16816(acc[nb], al0, al1, al2, al3, bh0, bh1);
            }
        }
    }

    // ---- epilogue: warp tile 16 px x 64 oc -> out[b][oc][y][px] ----
    {
        int px0 = wid * 16 + (lane >> 2);
        int oc0 = 2 * (lane & 3);
        float* ob = out + ((size_t)b * OCC * HH + y) * WW;
        #pragma unroll
        for (int nbk = 0; nbk < 8; nbk++) {
            int oc = nbk * 8 + oc0;
            ob[(size_t)oc * HW + px0]           = acc[nbk][0];
            ob[(size_t)(oc + 1) * HW + px0]     = acc[nbk][1];
            ob[(size_t)oc * HW + px0 + 8]       = acc[nbk][2];
            ob[(size_t)(oc + 1) * HW + px0 + 8] = acc[nbk][3];
        }
    }
}

extern "C" void kernel_launch(void* const* d_in, const int* in_sizes, int n_in,
                              void* d_out, int out_size) {
    const float* input  = (const float*)d_in[0];
    const float* offset = (const float*)d_in[1];
    const float* mask   = (const float*)d_in[2];
    const float* weight = (const float*)d_in[3];
    const float* bias   = (const float*)d_in[4];
    float* out = (float*)d_out;

    nhwc_kernel<<<BB * HH, 256>>>(input);
    wprep_kernel<<<72, 256>>>(weight);

    cudaFuncSetAttribute(dcn_mma_kernel,
                         cudaFuncAttributeMaxDynamicSharedMemorySize, SM_TOTAL);
    dim3 grid(1, HH, BB);
    dcn_mma_kernel<<<grid, 256, SM_TOTAL>>>(offset, mask, bias, out);
}